// round 1
// baseline (speedup 1.0000x reference)
#include <cuda_runtime.h>
#include <math.h>

// ---------------- problem constants ----------------
#define T_LEN 4096
#define DM    2048
#define DI    4096
#define NH    64
#define HD    64
#define DS    128
#define CHUNK 256
#define NC    16            // T_LEN / CHUNK
#define CONVD 4352          // DI + 2*DS
#define DPROJ 8512          // 2*DI + 2*DS + NH
#define RMS_EPS 1e-5f

// ---------------- scratch (static device memory, no allocs) ----------------
static __device__ float g_zxbcdt[(size_t)T_LEN * DPROJ];   // in_proj output
static __device__ float g_xbc[(size_t)T_LEN * CONVD];      // conv+silu output
static __device__ float g_dt[T_LEN * NH];                  // softplus(dt)
static __device__ float g_dacs[T_LEN * NH];                // cumsum(dt*A) within chunk
static __device__ float g_cb[NC * CHUNK * CHUNK];          // C @ B^T per chunk
static __device__ float g_states[NC * NH * HD * DS];
static __device__ float g_sprev[NC * NH * HD * DS];
static __device__ float g_y[(size_t)T_LEN * DI];

// =====================================================================
// Generic fp32 NT GEMM: C[M,N] = A[M,K] @ B[N,K]^T, row-major everything.
// 128x128 block tile, BK=8, 256 threads, 8x8 micro-tile per thread.
// M must be a multiple of 128; N guarded (must be multiple of 4); K mult of 8.
// =====================================================================
__device__ __forceinline__ void sgemm_nt_body(
    const float* __restrict__ A, const float* __restrict__ B,
    float* __restrict__ C, int M, int N, int K)
{
    __shared__ float As[8][128];
    __shared__ float Bs[8][128];
    const int bn = blockIdx.x * 128;
    const int bm = blockIdx.y * 128;
    const int tid = threadIdx.x;
    const int tx = tid & 15;
    const int ty = tid >> 4;
    const int lr = tid >> 1;          // 0..127: row within tile for loading
    const int lc = (tid & 1) * 4;     // 0 or 4: k-offset for loading

    const float* Ap = A + (size_t)(bm + lr) * K + lc;
    const float* Bp = B + (size_t)(bn + lr) * K + lc;
    const bool bvalid = (bn + lr) < N;

    float acc[8][8];
#pragma unroll
    for (int i = 0; i < 8; ++i)
#pragma unroll
        for (int j = 0; j < 8; ++j) acc[i][j] = 0.f;

    for (int k0 = 0; k0 < K; k0 += 8) {
        float4 av = *(const float4*)(Ap + k0);
        float4 bv = bvalid ? *(const float4*)(Bp + k0) : make_float4(0.f, 0.f, 0.f, 0.f);
        As[lc + 0][lr] = av.x; As[lc + 1][lr] = av.y;
        As[lc + 2][lr] = av.z; As[lc + 3][lr] = av.w;
        Bs[lc + 0][lr] = bv.x; Bs[lc + 1][lr] = bv.y;
        Bs[lc + 2][lr] = bv.z; Bs[lc + 3][lr] = bv.w;
        __syncthreads();
#pragma unroll
        for (int kk = 0; kk < 8; ++kk) {
            float4 a0 = *(const float4*)&As[kk][ty * 4];
            float4 a1 = *(const float4*)&As[kk][64 + ty * 4];
            float4 b0 = *(const float4*)&Bs[kk][tx * 4];
            float4 b1 = *(const float4*)&Bs[kk][64 + tx * 4];
            float a[8] = {a0.x, a0.y, a0.z, a0.w, a1.x, a1.y, a1.z, a1.w};
            float b[8] = {b0.x, b0.y, b0.z, b0.w, b1.x, b1.y, b1.z, b1.w};
#pragma unroll
            for (int i = 0; i < 8; ++i)
#pragma unroll
                for (int j = 0; j < 8; ++j)
                    acc[i][j] = fmaf(a[i], b[j], acc[i][j]);
        }
        __syncthreads();
    }

#pragma unroll
    for (int i = 0; i < 8; ++i) {
        int r = bm + ((i < 4) ? (ty * 4 + i) : (64 + ty * 4 + i - 4));
#pragma unroll
        for (int jh = 0; jh < 2; ++jh) {
            int cidx = bn + ((jh == 0) ? (tx * 4) : (64 + tx * 4));
            if (cidx < N) {
                int jb = jh * 4;
                *(float4*)&C[(size_t)r * N + cidx] =
                    make_float4(acc[i][jb], acc[i][jb + 1], acc[i][jb + 2], acc[i][jb + 3]);
            }
        }
    }
}

__global__ __launch_bounds__(256) void gemm_in_kernel(
    const float* __restrict__ hs, const float* __restrict__ w)
{
    sgemm_nt_body(hs, w, g_zxbcdt, T_LEN, DPROJ, DM);
}

__global__ __launch_bounds__(256) void gemm_out_kernel(
    const float* __restrict__ w, float* __restrict__ out)
{
    sgemm_nt_body(g_y, w, out, T_LEN, DM, DI);
}

// =====================================================================
// Causal depthwise conv (width 4) + SiLU over the xBC slice of zxbcdt.
// grid: (CONVD/256, T_LEN), 256 threads
// =====================================================================
__global__ void conv_silu_kernel(const float* __restrict__ conv_w,
                                 const float* __restrict__ conv_b)
{
    const int c = blockIdx.x * 256 + threadIdx.x;
    const int t = blockIdx.y;
    float acc = conv_b[c];
#pragma unroll
    for (int k = 0; k < 4; ++k) {
        int tt = t - 3 + k;
        if (tt >= 0)
            acc = fmaf(conv_w[c * 4 + k],
                       g_zxbcdt[(size_t)tt * DPROJ + DI + c], acc);
    }
    float s = acc / (1.f + expf(-acc));          // silu
    g_xbc[(size_t)t * CONVD + c] = s;
}

// =====================================================================
// softplus(dt + bias), then inclusive scan of dt*A within each chunk.
// grid: NC*NH blocks, CHUNK threads
// =====================================================================
__global__ void dt_scan_kernel(const float* __restrict__ Av,
                               const float* __restrict__ dtb)
{
    const int c = blockIdx.x / NH, h = blockIdx.x % NH;
    const int l = threadIdx.x;
    const int t = c * CHUNK + l;
    float xv = g_zxbcdt[(size_t)t * DPROJ + DI + CONVD + h] + dtb[h];
    float dtv = (xv > 15.f) ? xv : log1pf(expf(xv));
    g_dt[t * NH + h] = dtv;

    __shared__ float sb[CHUNK];
    sb[l] = dtv * Av[h];
    __syncthreads();
    for (int off = 1; off < CHUNK; off <<= 1) {
        float v = (l >= off) ? sb[l - off] : 0.f;
        __syncthreads();
        sb[l] += v;
        __syncthreads();
    }
    g_dacs[t * NH + h] = sb[l];
}

// =====================================================================
// CB[c,l,s] = sum_n C[c,l,n] * B[c,s,n]  (ngroups = 1)
// grid: (4,4,NC) -> 64x64 tiles; upper-triangular tiles skipped (never read)
// =====================================================================
__global__ __launch_bounds__(256) void cb_kernel()
{
    if (blockIdx.x > blockIdx.y) return;           // strictly-upper tiles unused
    const int chunk = blockIdx.z;
    const int lt = blockIdx.y * 64, st = blockIdx.x * 64;
    const int tid = threadIdx.x, tx = tid & 15, ty = tid >> 4;
    const int t0 = chunk * CHUNK;
    __shared__ float Cs[16][65];
    __shared__ float Bs[16][65];
    float acc[4][4] = {};
    const int lr = tid >> 2, kc = (tid & 3) * 4;

    for (int k0 = 0; k0 < DS; k0 += 16) {
        __syncthreads();
        float4 cv = *(const float4*)&g_xbc[(size_t)(t0 + lt + lr) * CONVD + DI + DS + k0 + kc];
        Cs[kc + 0][lr] = cv.x; Cs[kc + 1][lr] = cv.y;
        Cs[kc + 2][lr] = cv.z; Cs[kc + 3][lr] = cv.w;
        float4 bv = *(const float4*)&g_xbc[(size_t)(t0 + st + lr) * CONVD + DI + k0 + kc];
        Bs[kc + 0][lr] = bv.x; Bs[kc + 1][lr] = bv.y;
        Bs[kc + 2][lr] = bv.z; Bs[kc + 3][lr] = bv.w;
        __syncthreads();
#pragma unroll
        for (int kk = 0; kk < 16; ++kk) {
            float a[4], b[4];
#pragma unroll
            for (int i = 0; i < 4; ++i) a[i] = Cs[kk][ty * 4 + i];
#pragma unroll
            for (int j = 0; j < 4; ++j) b[j] = Bs[kk][tx * 4 + j];
#pragma unroll
            for (int i = 0; i < 4; ++i)
#pragma unroll
                for (int j = 0; j < 4; ++j)
                    acc[i][j] = fmaf(a[i], b[j], acc[i][j]);
        }
    }
    float* dst = g_cb + chunk * CHUNK * CHUNK;
#pragma unroll
    for (int i = 0; i < 4; ++i)
#pragma unroll
        for (int j = 0; j < 4; ++j)
            dst[(lt + ty * 4 + i) * CHUNK + st + tx * 4 + j] = acc[i][j];
}

// =====================================================================
// y_intra[c,l,h,p] = sum_s  CB[l,s]*exp(dAcs[l]-dAcs[s])*dt[s]*[s<=l] * x[s,h,p]
// grid: (4 l-tiles, NH, NC), 256 threads, 64x64 output tile
// =====================================================================
__global__ __launch_bounds__(256) void yintra_kernel()
{
    const int chunk = blockIdx.z, h = blockIdx.y, lt = blockIdx.x * 64;
    const int tid = threadIdx.x, tx = tid & 15, ty = tid >> 4;
    const int t0 = chunk * CHUNK;
    __shared__ float Ws[64][65];
    __shared__ float Xs[64][64];
    __shared__ float dal[64], das[64], dts[64];
    float acc[4][4] = {};
    if (tid < 64) dal[tid] = g_dacs[(t0 + lt + tid) * NH + h];
    const float* cbp = g_cb + chunk * CHUNK * CHUNK;

    for (int st = 0; st <= lt; st += 64) {
        __syncthreads();
        if (tid < 64) {
            das[tid] = g_dacs[(t0 + st + tid) * NH + h];
            dts[tid] = g_dt[(t0 + st + tid) * NH + h];
        }
        __syncthreads();
        // weight tile
#pragma unroll
        for (int i = 0; i < 4; ++i) {
            int l = lt + ty * 4 + i;
#pragma unroll
            for (int j = 0; j < 4; ++j) {
                int s = st + tx * 4 + j;
                float w = 0.f;
                if (s <= l)
                    w = cbp[l * CHUNK + s] *
                        expf(dal[ty * 4 + i] - das[tx * 4 + j]) * dts[tx * 4 + j];
                Ws[ty * 4 + i][tx * 4 + j] = w;
            }
        }
        // x tile
#pragma unroll
        for (int rr = 0; rr < 4; ++rr) {
            int srow = rr * 16 + ty;
            *(float4*)&Xs[srow][tx * 4] =
                *(const float4*)&g_xbc[(size_t)(t0 + st + srow) * CONVD + h * HD + tx * 4];
        }
        __syncthreads();
#pragma unroll
        for (int kk = 0; kk < 64; ++kk) {
            float4 b = *(const float4*)&Xs[kk][tx * 4];
#pragma unroll
            for (int i = 0; i < 4; ++i) {
                float a = Ws[ty * 4 + i][kk];
                acc[i][0] = fmaf(a, b.x, acc[i][0]);
                acc[i][1] = fmaf(a, b.y, acc[i][1]);
                acc[i][2] = fmaf(a, b.z, acc[i][2]);
                acc[i][3] = fmaf(a, b.w, acc[i][3]);
            }
        }
    }
#pragma unroll
    for (int i = 0; i < 4; ++i) {
        int t = t0 + lt + ty * 4 + i;
        *(float4*)&g_y[(size_t)t * DI + h * HD + tx * 4] =
            make_float4(acc[i][0], acc[i][1], acc[i][2], acc[i][3]);
    }
}

// =====================================================================
// states[c,h,p,n] = sum_l B[c,l,n] * x[c,l,h,p] * dt[l]*exp(dAcs[last]-dAcs[l])
// grid: (NH, NC), 256 threads, 64x128 output
// =====================================================================
__global__ __launch_bounds__(256) void states_kernel()
{
    const int h = blockIdx.x, chunk = blockIdx.y;
    const int tid = threadIdx.x, tx = tid & 15, ty = tid >> 4;
    const int t0 = chunk * CHUNK;
    __shared__ float Xt[32][64];
    __shared__ float Bt[32][128];
    __shared__ float coef[32];
    float acc[4][8] = {};
    const float dacs_last = g_dacs[(t0 + CHUNK - 1) * NH + h];

    for (int l0 = 0; l0 < CHUNK; l0 += 32) {
        __syncthreads();
        if (tid < 32) {
            int t = t0 + l0 + tid;
            coef[tid] = g_dt[t * NH + h] * expf(dacs_last - g_dacs[t * NH + h]);
        }
        {
            int r = tid >> 3, c = (tid & 7) * 8;
            *(float4*)&Xt[r][c] =
                *(const float4*)&g_xbc[(size_t)(t0 + l0 + r) * CONVD + h * HD + c];
            *(float4*)&Xt[r][c + 4] =
                *(const float4*)&g_xbc[(size_t)(t0 + l0 + r) * CONVD + h * HD + c + 4];
            int c2 = (tid & 7) * 16;
#pragma unroll
            for (int q = 0; q < 4; ++q)
                *(float4*)&Bt[r][c2 + q * 4] =
                    *(const float4*)&g_xbc[(size_t)(t0 + l0 + r) * CONVD + DI + c2 + q * 4];
        }
        __syncthreads();
#pragma unroll
        for (int kk = 0; kk < 32; ++kk) {
            float ck = coef[kk];
            float a[4];
#pragma unroll
            for (int i = 0; i < 4; ++i) a[i] = Xt[kk][ty * 4 + i] * ck;
            float4 b0 = *(const float4*)&Bt[kk][tx * 8];
            float4 b1 = *(const float4*)&Bt[kk][tx * 8 + 4];
            float b[8] = {b0.x, b0.y, b0.z, b0.w, b1.x, b1.y, b1.z, b1.w};
#pragma unroll
            for (int i = 0; i < 4; ++i)
#pragma unroll
                for (int j = 0; j < 8; ++j)
                    acc[i][j] = fmaf(a[i], b[j], acc[i][j]);
        }
    }
    float* dst = g_states + (size_t)(chunk * NH + h) * HD * DS;
#pragma unroll
    for (int i = 0; i < 4; ++i) {
        int p = ty * 4 + i;
#pragma unroll
        for (int j = 0; j < 8; j += 4)
            *(float4*)&dst[p * DS + tx * 8 + j] =
                make_float4(acc[i][j], acc[i][j + 1], acc[i][j + 2], acc[i][j + 3]);
    }
}

// =====================================================================
// Sequential scan over chunks: S_prev[c] = cd[c-1]*S_prev[c-1] + states[c-1]
// =====================================================================
__global__ void scan_kernel()
{
    const int idx = blockIdx.x * blockDim.x + threadIdx.x;  // NH*HD*DS
    const int h = idx / (HD * DS);
    float S = 0.f;
#pragma unroll
    for (int c = 0; c < NC; ++c) {
        g_sprev[(size_t)c * (NH * HD * DS) + idx] = S;
        float cd = expf(g_dacs[(c * CHUNK + CHUNK - 1) * NH + h]);
        S = fmaf(cd, S, g_states[(size_t)c * (NH * HD * DS) + idx]);
    }
}

// =====================================================================
// y_inter + combine: y = (y_intra + (C@S_prev)*exp(dAcs) + x*D) * silu(z)
// grid: (4 l-tiles, NH, NC), 256 threads, 64x64 output tile, K = DS
// =====================================================================
__global__ __launch_bounds__(256) void yinter_kernel(const float* __restrict__ Dp)
{
    const int chunk = blockIdx.z, h = blockIdx.y, lt = blockIdx.x * 64;
    const int tid = threadIdx.x, tx = tid & 15, ty = tid >> 4;
    const int t0 = chunk * CHUNK;
    __shared__ float Cs[16][65];
    __shared__ float Ss[16][65];
    float acc[4][4] = {};
    const float* sp = g_sprev + (size_t)(chunk * NH + h) * HD * DS;
    const int lr = tid >> 2, nc = (tid & 3) * 4;

    for (int n0 = 0; n0 < DS; n0 += 16) {
        __syncthreads();
        {
            float4 cv = *(const float4*)&g_xbc[(size_t)(t0 + lt + lr) * CONVD + DI + DS + n0 + nc];
            Cs[nc + 0][lr] = cv.x; Cs[nc + 1][lr] = cv.y;
            Cs[nc + 2][lr] = cv.z; Cs[nc + 3][lr] = cv.w;
            float4 sv = *(const float4*)&sp[lr * DS + n0 + nc];
            Ss[nc + 0][lr] = sv.x; Ss[nc + 1][lr] = sv.y;
            Ss[nc + 2][lr] = sv.z; Ss[nc + 3][lr] = sv.w;
        }
        __syncthreads();
#pragma unroll
        for (int kk = 0; kk < 16; ++kk) {
            float a[4], b[4];
#pragma unroll
            for (int i = 0; i < 4; ++i) a[i] = Cs[kk][ty * 4 + i];
#pragma unroll
            for (int j = 0; j < 4; ++j) b[j] = Ss[kk][tx * 4 + j];
#pragma unroll
            for (int i = 0; i < 4; ++i)
#pragma unroll
                for (int j = 0; j < 4; ++j)
                    acc[i][j] = fmaf(a[i], b[j], acc[i][j]);
        }
    }

    const float Dh = Dp[h];
#pragma unroll
    for (int i = 0; i < 4; ++i) {
        int t = t0 + lt + ty * 4 + i;
        float esc = expf(g_dacs[t * NH + h]);
#pragma unroll
        for (int j = 0; j < 4; ++j) {
            int col = h * HD + tx * 4 + j;
            float x = g_xbc[(size_t)t * CONVD + col];
            float z = g_zxbcdt[(size_t)t * DPROJ + col];
            float yv = g_y[(size_t)t * DI + col] + acc[i][j] * esc + x * Dh;
            float gate = z / (1.f + expf(-z));
            g_y[(size_t)t * DI + col] = yv * gate;
        }
    }
}

// =====================================================================
// RMSNorm in place over DI per row
// =====================================================================
__global__ void rmsnorm_kernel(const float* __restrict__ norm_w)
{
    const int t = blockIdx.x;
    float* row = g_y + (size_t)t * DI;
    float ss = 0.f;
    for (int c = threadIdx.x; c < DI; c += 256) {
        float v = row[c];
        ss = fmaf(v, v, ss);
    }
    __shared__ float red[256];
    red[threadIdx.x] = ss;
    __syncthreads();
    for (int o = 128; o > 0; o >>= 1) {
        if (threadIdx.x < o) red[threadIdx.x] += red[threadIdx.x + o];
        __syncthreads();
    }
    const float r = rsqrtf(red[0] / (float)DI + RMS_EPS);
    for (int c = threadIdx.x; c < DI; c += 256)
        row[c] = row[c] * r * norm_w[c];
}

// =====================================================================
// launch
// =====================================================================
extern "C" void kernel_launch(void* const* d_in, const int* in_sizes, int n_in,
                              void* d_out, int out_size)
{
    const float* hs   = (const float*)d_in[0];
    const float* win  = (const float*)d_in[1];
    const float* cw   = (const float*)d_in[2];
    const float* cbv  = (const float*)d_in[3];
    const float* Av   = (const float*)d_in[4];
    const float* Dp   = (const float*)d_in[5];
    const float* dtb  = (const float*)d_in[6];
    const float* nw   = (const float*)d_in[7];
    const float* wout = (const float*)d_in[8];
    float* out = (float*)d_out;

    gemm_in_kernel<<<dim3((DPROJ + 127) / 128, T_LEN / 128), 256>>>(hs, win);
    conv_silu_kernel<<<dim3(CONVD / 256, T_LEN), 256>>>(cw, cbv);
    dt_scan_kernel<<<NC * NH, CHUNK>>>(Av, dtb);
    cb_kernel<<<dim3(4, 4, NC), 256>>>();
    yintra_kernel<<<dim3(4, NH, NC), 256>>>();
    states_kernel<<<dim3(NH, NC), 256>>>();
    scan_kernel<<<(NH * HD * DS) / 256, 256>>>();
    yinter_kernel<<<dim3(4, NH, NC), 256>>>(Dp);
    rmsnorm_kernel<<<T_LEN, 256>>>(nw);
    gemm_out_kernel<<<dim3(DM / 128, T_LEN / 128), 256>>>(wout, out);
}

// round 8
// speedup vs baseline: 1.0894x; 1.0894x over previous
#include <cuda_runtime.h>
#include <math.h>

// ---------------- problem constants ----------------
#define T_LEN 4096
#define DM    2048
#define DI    4096
#define NH    64
#define HD    64
#define DS    128
#define CHUNK 256
#define NC    16
#define CONVD 4352
#define DPROJ 8512
#define RMS_EPS 1e-5f

// ---------------- scratch (static device memory, no allocs) ----------------
static __device__ float g_zxbcdt[(size_t)T_LEN * DPROJ];
static __device__ float g_xbc[(size_t)T_LEN * CONVD];
static __device__ float g_dt[T_LEN * NH];
static __device__ float g_dacs[T_LEN * NH];
static __device__ float g_cb[NC * CHUNK * CHUNK];
static __device__ float g_states[NC * NH * HD * DS];
static __device__ float g_sprev[NC * NH * HD * DS];
static __device__ float g_y[(size_t)T_LEN * DI];

// =====================================================================
// fp32 NT GEMM, double-buffered: C[M,N] = A[M,K] @ B[N,K]^T, row-major.
// 128x128 CTA tile, BK=16, 256 threads, 8x8 micro-tile per thread.
// Two smem stages; register prefetch of stage i+1 overlaps compute on i.
// M multiple of 128; N guarded; K multiple of 16.
// =====================================================================
#define BK2 16

__device__ __forceinline__ void sgemm_db_body(
    const float* __restrict__ A, const float* __restrict__ B,
    float* __restrict__ C, int M, int N, int K)
{
    __shared__ float As[2][BK2][128];
    __shared__ float Bs[2][BK2][128];
    const int bn = blockIdx.x * 128;
    const int bm = blockIdx.y * 128;
    const int tid = threadIdx.x;
    const int tx = tid & 15;
    const int ty = tid >> 4;
    const int lr = tid >> 1;          // 0..127: row within tile for loading
    const int lc = (tid & 1) * 8;     // 0 or 8: k-offset for loading

    const float* Ap = A + (size_t)(bm + lr) * K + lc;
    const float* Bp = B + (size_t)(bn + lr) * K + lc;
    const bool bvalid = (bn + lr) < N;
    const int NI = K / BK2;

    float acc[8][8];
#pragma unroll
    for (int i = 0; i < 8; ++i)
#pragma unroll
        for (int j = 0; j < 8; ++j) acc[i][j] = 0.f;

    float4 ra0, ra1, rb0, rb1;
    const float4 z4 = make_float4(0.f, 0.f, 0.f, 0.f);

#define PF(it) do {                                                   \
        const float* _a = Ap + (it) * BK2;                            \
        ra0 = *(const float4*)(_a);                                   \
        ra1 = *(const float4*)(_a + 4);                               \
        if (bvalid) {                                                 \
            const float* _b = Bp + (it) * BK2;                        \
            rb0 = *(const float4*)(_b);                               \
            rb1 = *(const float4*)(_b + 4);                           \
        } else { rb0 = z4; rb1 = z4; }                                \
    } while (0)

#define ST(buf) do {                                                  \
        As[buf][lc + 0][lr] = ra0.x; As[buf][lc + 1][lr] = ra0.y;     \
        As[buf][lc + 2][lr] = ra0.z; As[buf][lc + 3][lr] = ra0.w;     \
        As[buf][lc + 4][lr] = ra1.x; As[buf][lc + 5][lr] = ra1.y;     \
        As[buf][lc + 6][lr] = ra1.z; As[buf][lc + 7][lr] = ra1.w;     \
        Bs[buf][lc + 0][lr] = rb0.x; Bs[buf][lc + 1][lr] = rb0.y;     \
        Bs[buf][lc + 2][lr] = rb0.z; Bs[buf][lc + 3][lr] = rb0.w;     \
        Bs[buf][lc + 4][lr] = rb1.x; Bs[buf][lc + 5][lr] = rb1.y;     \
        Bs[buf][lc + 6][lr] = rb1.z; Bs[buf][lc + 7][lr] = rb1.w;     \
    } while (0)

    PF(0);
    ST(0);
    __syncthreads();

    for (int it = 0; it < NI; ++it) {
        const int buf = it & 1;
        if (it + 1 < NI) PF(it + 1);
#pragma unroll
        for (int kk = 0; kk < BK2; ++kk) {
            float4 a0 = *(const float4*)&As[buf][kk][ty * 4];
            float4 a1 = *(const float4*)&As[buf][kk][64 + ty * 4];
            float4 b0 = *(const float4*)&Bs[buf][kk][tx * 4];
            float4 b1 = *(const float4*)&Bs[buf][kk][64 + tx * 4];
            float a[8] = {a0.x, a0.y, a0.z, a0.w, a1.x, a1.y, a1.z, a1.w};
            float b[8] = {b0.x, b0.y, b0.z, b0.w, b1.x, b1.y, b1.z, b1.w};
#pragma unroll
            for (int i = 0; i < 8; ++i)
#pragma unroll
                for (int j = 0; j < 8; ++j)
                    acc[i][j] = fmaf(a[i], b[j], acc[i][j]);
        }
        if (it + 1 < NI) {
            ST(buf ^ 1);
            __syncthreads();
        }
    }

#pragma unroll
    for (int i = 0; i < 8; ++i) {
        int r = bm + ((i < 4) ? (ty * 4 + i) : (64 + ty * 4 + i - 4));
#pragma unroll
        for (int jh = 0; jh < 2; ++jh) {
            int cidx = bn + ((jh == 0) ? (tx * 4) : (64 + tx * 4));
            if (cidx < N) {
                int jb = jh * 4;
                *(float4*)&C[(size_t)r * N + cidx] =
                    make_float4(acc[i][jb], acc[i][jb + 1], acc[i][jb + 2], acc[i][jb + 3]);
            }
        }
    }
#undef PF
#undef ST
}

__global__ __launch_bounds__(256) void gemm_in_kernel(
    const float* __restrict__ hs, const float* __restrict__ w)
{
    sgemm_db_body(hs, w, g_zxbcdt, T_LEN, DPROJ, DM);
}

__global__ __launch_bounds__(256) void gemm_out_kernel(
    const float* __restrict__ w, float* __restrict__ out)
{
    sgemm_db_body(g_y, w, out, T_LEN, DM, DI);
}

// =====================================================================
// Causal depthwise conv (width 4) + SiLU over the xBC slice of zxbcdt.
// =====================================================================
__global__ void conv_silu_kernel(const float* __restrict__ conv_w,
                                 const float* __restrict__ conv_b)
{
    const int c = blockIdx.x * 256 + threadIdx.x;
    const int t = blockIdx.y;
    float acc = conv_b[c];
#pragma unroll
    for (int k = 0; k < 4; ++k) {
        int tt = t - 3 + k;
        if (tt >= 0)
            acc = fmaf(conv_w[c * 4 + k],
                       g_zxbcdt[(size_t)tt * DPROJ + DI + c], acc);
    }
    g_xbc[(size_t)t * CONVD + c] = acc / (1.f + expf(-acc));
}

// =====================================================================
// softplus(dt + bias), then inclusive scan of dt*A within each chunk.
// =====================================================================
__global__ void dt_scan_kernel(const float* __restrict__ Av,
                               const float* __restrict__ dtb)
{
    const int c = blockIdx.x / NH, h = blockIdx.x % NH;
    const int l = threadIdx.x;
    const int t = c * CHUNK + l;
    float xv = g_zxbcdt[(size_t)t * DPROJ + DI + CONVD + h] + dtb[h];
    float dtv = (xv > 15.f) ? xv : log1pf(expf(xv));
    g_dt[t * NH + h] = dtv;

    __shared__ float sb[CHUNK];
    sb[l] = dtv * Av[h];
    __syncthreads();
    for (int off = 1; off < CHUNK; off <<= 1) {
        float v = (l >= off) ? sb[l - off] : 0.f;
        __syncthreads();
        sb[l] += v;
        __syncthreads();
    }
    g_dacs[t * NH + h] = sb[l];
}

// =====================================================================
// CB[c,l,s] = sum_n C[c,l,n] * B[c,s,n]  (lower-triangular tiles only)
// =====================================================================
__global__ __launch_bounds__(256) void cb_kernel()
{
    if (blockIdx.x > blockIdx.y) return;
    const int chunk = blockIdx.z;
    const int lt = blockIdx.y * 64, st = blockIdx.x * 64;
    const int tid = threadIdx.x, tx = tid & 15, ty = tid >> 4;
    const int t0 = chunk * CHUNK;
    __shared__ float Cs[16][65];
    __shared__ float Bs[16][65];
    float acc[4][4] = {};
    const int lr = tid >> 2, kc = (tid & 3) * 4;

    for (int k0 = 0; k0 < DS; k0 += 16) {
        __syncthreads();
        float4 cv = *(const float4*)&g_xbc[(size_t)(t0 + lt + lr) * CONVD + DI + DS + k0 + kc];
        Cs[kc + 0][lr] = cv.x; Cs[kc + 1][lr] = cv.y;
        Cs[kc + 2][lr] = cv.z; Cs[kc + 3][lr] = cv.w;
        float4 bv = *(const float4*)&g_xbc[(size_t)(t0 + st + lr) * CONVD + DI + k0 + kc];
        Bs[kc + 0][lr] = bv.x; Bs[kc + 1][lr] = bv.y;
        Bs[kc + 2][lr] = bv.z; Bs[kc + 3][lr] = bv.w;
        __syncthreads();
#pragma unroll
        for (int kk = 0; kk < 16; ++kk) {
            float a[4], b[4];
#pragma unroll
            for (int i = 0; i < 4; ++i) a[i] = Cs[kk][ty * 4 + i];
#pragma unroll
            for (int j = 0; j < 4; ++j) b[j] = Bs[kk][tx * 4 + j];
#pragma unroll
            for (int i = 0; i < 4; ++i)
#pragma unroll
                for (int j = 0; j < 4; ++j)
                    acc[i][j] = fmaf(a[i], b[j], acc[i][j]);
        }
    }
    float* dst = g_cb + chunk * CHUNK * CHUNK;
#pragma unroll
    for (int i = 0; i < 4; ++i)
#pragma unroll
        for (int j = 0; j < 4; ++j)
            dst[(lt + ty * 4 + i) * CHUNK + st + tx * 4 + j] = acc[i][j];
}

// =====================================================================
// y_intra
// =====================================================================
__global__ __launch_bounds__(256) void yintra_kernel()
{
    const int chunk = blockIdx.z, h = blockIdx.y, lt = blockIdx.x * 64;
    const int tid = threadIdx.x, tx = tid & 15, ty = tid >> 4;
    const int t0 = chunk * CHUNK;
    __shared__ float Ws[64][65];
    __shared__ float Xs[64][64];
    __shared__ float dal[64], das[64], dts[64];
    float acc[4][4] = {};
    if (tid < 64) dal[tid] = g_dacs[(t0 + lt + tid) * NH + h];
    const float* cbp = g_cb + chunk * CHUNK * CHUNK;

    for (int st = 0; st <= lt; st += 64) {
        __syncthreads();
        if (tid < 64) {
            das[tid] = g_dacs[(t0 + st + tid) * NH + h];
            dts[tid] = g_dt[(t0 + st + tid) * NH + h];
        }
        __syncthreads();
#pragma unroll
        for (int i = 0; i < 4; ++i) {
            int l = lt + ty * 4 + i;
#pragma unroll
            for (int j = 0; j < 4; ++j) {
                int s = st + tx * 4 + j;
                float w = 0.f;
                if (s <= l)
                    w = cbp[l * CHUNK + s] *
                        expf(dal[ty * 4 + i] - das[tx * 4 + j]) * dts[tx * 4 + j];
                Ws[ty * 4 + i][tx * 4 + j] = w;
            }
        }
#pragma unroll
        for (int rr = 0; rr < 4; ++rr) {
            int srow = rr * 16 + ty;
            *(float4*)&Xs[srow][tx * 4] =
                *(const float4*)&g_xbc[(size_t)(t0 + st + srow) * CONVD + h * HD + tx * 4];
        }
        __syncthreads();
#pragma unroll
        for (int kk = 0; kk < 64; ++kk) {
            float4 b = *(const float4*)&Xs[kk][tx * 4];
#pragma unroll
            for (int i = 0; i < 4; ++i) {
                float a = Ws[ty * 4 + i][kk];
                acc[i][0] = fmaf(a, b.x, acc[i][0]);
                acc[i][1] = fmaf(a, b.y, acc[i][1]);
                acc[i][2] = fmaf(a, b.z, acc[i][2]);
                acc[i][3] = fmaf(a, b.w, acc[i][3]);
            }
        }
    }
#pragma unroll
    for (int i = 0; i < 4; ++i) {
        int t = t0 + lt + ty * 4 + i;
        *(float4*)&g_y[(size_t)t * DI + h * HD + tx * 4] =
            make_float4(acc[i][0], acc[i][1], acc[i][2], acc[i][3]);
    }
}

// =====================================================================
// per-chunk states
// =====================================================================
__global__ __launch_bounds__(256) void states_kernel()
{
    const int h = blockIdx.x, chunk = blockIdx.y;
    const int tid = threadIdx.x, tx = tid & 15, ty = tid >> 4;
    const int t0 = chunk * CHUNK;
    __shared__ float Xt[32][64];
    __shared__ float Bt[32][128];
    __shared__ float coef[32];
    float acc[4][8] = {};
    const float dacs_last = g_dacs[(t0 + CHUNK - 1) * NH + h];

    for (int l0 = 0; l0 < CHUNK; l0 += 32) {
        __syncthreads();
        if (tid < 32) {
            int t = t0 + l0 + tid;
            coef[tid] = g_dt[t * NH + h] * expf(dacs_last - g_dacs[t * NH + h]);
        }
        {
            int r = tid >> 3, c = (tid & 7) * 8;
            *(float4*)&Xt[r][c] =
                *(const float4*)&g_xbc[(size_t)(t0 + l0 + r) * CONVD + h * HD + c];
            *(float4*)&Xt[r][c + 4] =
                *(const float4*)&g_xbc[(size_t)(t0 + l0 + r) * CONVD + h * HD + c + 4];
            int c2 = (tid & 7) * 16;
#pragma unroll
            for (int q = 0; q < 4; ++q)
                *(float4*)&Bt[r][c2 + q * 4] =
                    *(const float4*)&g_xbc[(size_t)(t0 + l0 + r) * CONVD + DI + c2 + q * 4];
        }
        __syncthreads();
#pragma unroll
        for (int kk = 0; kk < 32; ++kk) {
            float ck = coef[kk];
            float a[4];
#pragma unroll
            for (int i = 0; i < 4; ++i) a[i] = Xt[kk][ty * 4 + i] * ck;
            float4 b0 = *(const float4*)&Bt[kk][tx * 8];
            float4 b1 = *(const float4*)&Bt[kk][tx * 8 + 4];
            float b[8] = {b0.x, b0.y, b0.z, b0.w, b1.x, b1.y, b1.z, b1.w};
#pragma unroll
            for (int i = 0; i < 4; ++i)
#pragma unroll
                for (int j = 0; j < 8; ++j)
                    acc[i][j] = fmaf(a[i], b[j], acc[i][j]);
        }
    }
    float* dst = g_states + (size_t)(chunk * NH + h) * HD * DS;
#pragma unroll
    for (int i = 0; i < 4; ++i) {
        int p = ty * 4 + i;
#pragma unroll
        for (int j = 0; j < 8; j += 4)
            *(float4*)&dst[p * DS + tx * 8 + j] =
                make_float4(acc[i][j], acc[i][j + 1], acc[i][j + 2], acc[i][j + 3]);
    }
}

// =====================================================================
// cross-chunk scan
// =====================================================================
__global__ void scan_kernel()
{
    const int idx = blockIdx.x * blockDim.x + threadIdx.x;
    const int h = idx / (HD * DS);
    float S = 0.f;
#pragma unroll
    for (int c = 0; c < NC; ++c) {
        g_sprev[(size_t)c * (NH * HD * DS) + idx] = S;
        float cd = expf(g_dacs[(c * CHUNK + CHUNK - 1) * NH + h]);
        S = fmaf(cd, S, g_states[(size_t)c * (NH * HD * DS) + idx]);
    }
}

// =====================================================================
// y_inter + gate
// =====================================================================
__global__ __launch_bounds__(256) void yinter_kernel(const float* __restrict__ Dp)
{
    const int chunk = blockIdx.z, h = blockIdx.y, lt = blockIdx.x * 64;
    const int tid = threadIdx.x, tx = tid & 15, ty = tid >> 4;
    const int t0 = chunk * CHUNK;
    __shared__ float Cs[16][65];
    __shared__ float Ss[16][65];
    float acc[4][4] = {};
    const float* sp = g_sprev + (size_t)(chunk * NH + h) * HD * DS;
    const int lr = tid >> 2, nc = (tid & 3) * 4;

    for (int n0 = 0; n0 < DS; n0 += 16) {
        __syncthreads();
        {
            float4 cv = *(const float4*)&g_xbc[(size_t)(t0 + lt + lr) * CONVD + DI + DS + n0 + nc];
            Cs[nc + 0][lr] = cv.x; Cs[nc + 1][lr] = cv.y;
            Cs[nc + 2][lr] = cv.z; Cs[nc + 3][lr] = cv.w;
            float4 sv = *(const float4*)&sp[lr * DS + n0 + nc];
            Ss[nc + 0][lr] = sv.x; Ss[nc + 1][lr] = sv.y;
            Ss[nc + 2][lr] = sv.z; Ss[nc + 3][lr] = sv.w;
        }
        __syncthreads();
#pragma unroll
        for (int kk = 0; kk < 16; ++kk) {
            float a[4], b[4];
#pragma unroll
            for (int i = 0; i < 4; ++i) a[i] = Cs[kk][ty * 4 + i];
#pragma unroll
            for (int j = 0; j < 4; ++j) b[j] = Ss[kk][tx * 4 + j];
#pragma unroll
            for (int i = 0; i < 4; ++i)
#pragma unroll
                for (int j = 0; j < 4; ++j)
                    acc[i][j] = fmaf(a[i], b[j], acc[i][j]);
        }
    }

    const float Dh = Dp[h];
#pragma unroll
    for (int i = 0; i < 4; ++i) {
        int t = t0 + lt + ty * 4 + i;
        float esc = expf(g_dacs[t * NH + h]);
#pragma unroll
        for (int j = 0; j < 4; ++j) {
            int col = h * HD + tx * 4 + j;
            float x = g_xbc[(size_t)t * CONVD + col];
            float z = g_zxbcdt[(size_t)t * DPROJ + col];
            float yv = g_y[(size_t)t * DI + col] + acc[i][j] * esc + x * Dh;
            float gate = z / (1.f + expf(-z));
            g_y[(size_t)t * DI + col] = yv * gate;
        }
    }
}

// =====================================================================
// RMSNorm in place
// =====================================================================
__global__ void rmsnorm_kernel(const float* __restrict__ norm_w)
{
    const int t = blockIdx.x;
    float* row = g_y + (size_t)t * DI;
    float ss = 0.f;
    for (int c = threadIdx.x; c < DI; c += 256) {
        float v = row[c];
        ss = fmaf(v, v, ss);
    }
    __shared__ float red[256];
    red[threadIdx.x] = ss;
    __syncthreads();
    for (int o = 128; o > 0; o >>= 1) {
        if (threadIdx.x < o) red[threadIdx.x] += red[threadIdx.x + o];
        __syncthreads();
    }
    const float r = rsqrtf(red[0] / (float)DI + RMS_EPS);
    for (int c = threadIdx.x; c < DI; c += 256)
        row[c] = row[c] * r * norm_w[c];
}

// =====================================================================
// launch
// =====================================================================
extern "C" void kernel_launch(void* const* d_in, const int* in_sizes, int n_in,
                              void* d_out, int out_size)
{
    const float* hs   = (const float*)d_in[0];
    const float* win  = (const float*)d_in[1];
    const float* cw   = (const float*)d_in[2];
    const float* cbv  = (const float*)d_in[3];
    const float* Av   = (const float*)d_in[4];
    const float* Dp   = (const float*)d_in[5];
    const float* dtb  = (const float*)d_in[6];
    const float* nw   = (const float*)d_in[7];
    const float* wout = (const float*)d_in[8];
    float* out = (float*)d_out;

    gemm_in_kernel<<<dim3((DPROJ + 127) / 128, T_LEN / 128), 256>>>(hs, win);
    conv_silu_kernel<<<dim3(CONVD / 256, T_LEN), 256>>>(cw, cbv);
    dt_scan_kernel<<<NC * NH, CHUNK>>>(Av, dtb);
    cb_kernel<<<dim3(4, 4, NC), 256>>>();
    yintra_kernel<<<dim3(4, NH, NC), 256>>>();
    states_kernel<<<dim3(NH, NC), 256>>>();
    scan_kernel<<<(NH * HD * DS) / 256, 256>>>();
    yinter_kernel<<<dim3(4, NH, NC), 256>>>(Dp);
    rmsnorm_kernel<<<T_LEN, 256>>>(nw);
    gemm_out_kernel<<<dim3(DM / 128, T_LEN / 128), 256>>>(wout, out);
}

// round 9
// speedup vs baseline: 1.1227x; 1.0306x over previous
#include <cuda_runtime.h>
#include <math.h>

// ---------------- problem constants ----------------
#define T_LEN 4096
#define DM    2048
#define DI    4096
#define NH    64
#define HD    64
#define DS    128
#define CHUNK 256
#define NC    16
#define CONVD 4352
#define DPROJ 8512
#define RMS_EPS 1e-5f

// ---------------- scratch (static device memory, no allocs) ----------------
static __device__ float g_zxbcdt[(size_t)T_LEN * DPROJ];
static __device__ float g_xbc[(size_t)T_LEN * CONVD];
static __device__ float g_dt[T_LEN * NH];
static __device__ float g_dacs[T_LEN * NH];
static __device__ float g_cb[NC * CHUNK * CHUNK];
static __device__ float g_states[NC * NH * HD * DS];
static __device__ float g_sprev[NC * NH * HD * DS];
static __device__ float g_y[(size_t)T_LEN * DI];

// =====================================================================
// fp32 NT GEMM, double-buffered: C[M,N] = A[M,K] @ B[N,K]^T, row-major.
// 128x128 CTA tile, BK=16, 256 threads, 8x8 micro-tile per thread.
// Two smem stages; register prefetch of stage i+1 overlaps compute on i.
// __launch_bounds__(256,2): cap 128 regs -> 2 CTAs/SM (16 warps).
// =====================================================================
#define BK2 16

__device__ __forceinline__ void sgemm_db_body(
    const float* __restrict__ A, const float* __restrict__ B,
    float* __restrict__ C, int M, int N, int K)
{
    __shared__ float As[2][BK2][128];
    __shared__ float Bs[2][BK2][128];
    const int bn = blockIdx.x * 128;
    const int bm = blockIdx.y * 128;
    const int tid = threadIdx.x;
    const int tx = tid & 15;
    const int ty = tid >> 4;
    const int lr = tid >> 1;          // 0..127: row within tile for loading
    const int lc = (tid & 1) * 8;     // 0 or 8: k-offset for loading

    const float* Ap = A + (size_t)(bm + lr) * K + lc;
    const float* Bp = B + (size_t)(bn + lr) * K + lc;
    const bool bvalid = (bn + lr) < N;
    const int NI = K / BK2;

    float acc[8][8];
#pragma unroll
    for (int i = 0; i < 8; ++i)
#pragma unroll
        for (int j = 0; j < 8; ++j) acc[i][j] = 0.f;

    float4 ra0, ra1, rb0, rb1;
    const float4 z4 = make_float4(0.f, 0.f, 0.f, 0.f);

#define PF(it) do {                                                   \
        const float* _a = Ap + (it) * BK2;                            \
        ra0 = *(const float4*)(_a);                                   \
        ra1 = *(const float4*)(_a + 4);                               \
        if (bvalid) {                                                 \
            const float* _b = Bp + (it) * BK2;                        \
            rb0 = *(const float4*)(_b);                               \
            rb1 = *(const float4*)(_b + 4);                           \
        } else { rb0 = z4; rb1 = z4; }                                \
    } while (0)

#define ST(buf) do {                                                  \
        As[buf][lc + 0][lr] = ra0.x; As[buf][lc + 1][lr] = ra0.y;     \
        As[buf][lc + 2][lr] = ra0.z; As[buf][lc + 3][lr] = ra0.w;     \
        As[buf][lc + 4][lr] = ra1.x; As[buf][lc + 5][lr] = ra1.y;     \
        As[buf][lc + 6][lr] = ra1.z; As[buf][lc + 7][lr] = ra1.w;     \
        Bs[buf][lc + 0][lr] = rb0.x; Bs[buf][lc + 1][lr] = rb0.y;     \
        Bs[buf][lc + 2][lr] = rb0.z; Bs[buf][lc + 3][lr] = rb0.w;     \
        Bs[buf][lc + 4][lr] = rb1.x; Bs[buf][lc + 5][lr] = rb1.y;     \
        Bs[buf][lc + 6][lr] = rb1.z; Bs[buf][lc + 7][lr] = rb1.w;     \
    } while (0)

    PF(0);
    ST(0);
    __syncthreads();

    for (int it = 0; it < NI; ++it) {
        const int buf = it & 1;
        if (it + 1 < NI) PF(it + 1);
#pragma unroll
        for (int kk = 0; kk < BK2; ++kk) {
            float4 a0 = *(const float4*)&As[buf][kk][ty * 4];
            float4 a1 = *(const float4*)&As[buf][kk][64 + ty * 4];
            float4 b0 = *(const float4*)&Bs[buf][kk][tx * 4];
            float4 b1 = *(const float4*)&Bs[buf][kk][64 + tx * 4];
            float a[8] = {a0.x, a0.y, a0.z, a0.w, a1.x, a1.y, a1.z, a1.w};
            float b[8] = {b0.x, b0.y, b0.z, b0.w, b1.x, b1.y, b1.z, b1.w};
#pragma unroll
            for (int i = 0; i < 8; ++i)
#pragma unroll
                for (int j = 0; j < 8; ++j)
                    acc[i][j] = fmaf(a[i], b[j], acc[i][j]);
        }
        if (it + 1 < NI) {
            ST(buf ^ 1);
            __syncthreads();
        }
    }

#pragma unroll
    for (int i = 0; i < 8; ++i) {
        int r = bm + ((i < 4) ? (ty * 4 + i) : (64 + ty * 4 + i - 4));
#pragma unroll
        for (int jh = 0; jh < 2; ++jh) {
            int cidx = bn + ((jh == 0) ? (tx * 4) : (64 + tx * 4));
            if (cidx < N) {
                int jb = jh * 4;
                *(float4*)&C[(size_t)r * N + cidx] =
                    make_float4(acc[i][jb], acc[i][jb + 1], acc[i][jb + 2], acc[i][jb + 3]);
            }
        }
    }
#undef PF
#undef ST
}

__global__ __launch_bounds__(256, 2) void gemm_in_kernel(
    const float* __restrict__ hs, const float* __restrict__ w)
{
    sgemm_db_body(hs, w, g_zxbcdt, T_LEN, DPROJ, DM);
}

__global__ __launch_bounds__(256, 2) void gemm_out_kernel(
    const float* __restrict__ w, float* __restrict__ out)
{
    sgemm_db_body(g_y, w, out, T_LEN, DM, DI);
}

// =====================================================================
// Causal depthwise conv (width 4) + SiLU over the xBC slice of zxbcdt.
// =====================================================================
__global__ void conv_silu_kernel(const float* __restrict__ conv_w,
                                 const float* __restrict__ conv_b)
{
    const int c = blockIdx.x * 256 + threadIdx.x;
    const int t = blockIdx.y;
    float acc = conv_b[c];
#pragma unroll
    for (int k = 0; k < 4; ++k) {
        int tt = t - 3 + k;
        if (tt >= 0)
            acc = fmaf(conv_w[c * 4 + k],
                       g_zxbcdt[(size_t)tt * DPROJ + DI + c], acc);
    }
    g_xbc[(size_t)t * CONVD + c] = acc / (1.f + expf(-acc));
}

// =====================================================================
// softplus(dt + bias), then inclusive scan of dt*A within each chunk.
// =====================================================================
__global__ void dt_scan_kernel(const float* __restrict__ Av,
                               const float* __restrict__ dtb)
{
    const int c = blockIdx.x / NH, h = blockIdx.x % NH;
    const int l = threadIdx.x;
    const int t = c * CHUNK + l;
    float xv = g_zxbcdt[(size_t)t * DPROJ + DI + CONVD + h] + dtb[h];
    float dtv = (xv > 15.f) ? xv : log1pf(expf(xv));
    g_dt[t * NH + h] = dtv;

    __shared__ float sb[CHUNK];
    sb[l] = dtv * Av[h];
    __syncthreads();
    for (int off = 1; off < CHUNK; off <<= 1) {
        float v = (l >= off) ? sb[l - off] : 0.f;
        __syncthreads();
        sb[l] += v;
        __syncthreads();
    }
    g_dacs[t * NH + h] = sb[l];
}

// =====================================================================
// CB[c,l,s] = sum_n C[c,l,n] * B[c,s,n]  (lower-triangular tiles only)
// =====================================================================
__global__ __launch_bounds__(256) void cb_kernel()
{
    if (blockIdx.x > blockIdx.y) return;
    const int chunk = blockIdx.z;
    const int lt = blockIdx.y * 64, st = blockIdx.x * 64;
    const int tid = threadIdx.x, tx = tid & 15, ty = tid >> 4;
    const int t0 = chunk * CHUNK;
    __shared__ float Cs[16][65];
    __shared__ float Bs[16][65];
    float acc[4][4] = {};
    const int lr = tid >> 2, kc = (tid & 3) * 4;

    for (int k0 = 0; k0 < DS; k0 += 16) {
        __syncthreads();
        float4 cv = *(const float4*)&g_xbc[(size_t)(t0 + lt + lr) * CONVD + DI + DS + k0 + kc];
        Cs[kc + 0][lr] = cv.x; Cs[kc + 1][lr] = cv.y;
        Cs[kc + 2][lr] = cv.z; Cs[kc + 3][lr] = cv.w;
        float4 bv = *(const float4*)&g_xbc[(size_t)(t0 + st + lr) * CONVD + DI + k0 + kc];
        Bs[kc + 0][lr] = bv.x; Bs[kc + 1][lr] = bv.y;
        Bs[kc + 2][lr] = bv.z; Bs[kc + 3][lr] = bv.w;
        __syncthreads();
#pragma unroll
        for (int kk = 0; kk < 16; ++kk) {
            float a[4], b[4];
#pragma unroll
            for (int i = 0; i < 4; ++i) a[i] = Cs[kk][ty * 4 + i];
#pragma unroll
            for (int j = 0; j < 4; ++j) b[j] = Bs[kk][tx * 4 + j];
#pragma unroll
            for (int i = 0; i < 4; ++i)
#pragma unroll
                for (int j = 0; j < 4; ++j)
                    acc[i][j] = fmaf(a[i], b[j], acc[i][j]);
        }
    }
    float* dst = g_cb + chunk * CHUNK * CHUNK;
#pragma unroll
    for (int i = 0; i < 4; ++i)
#pragma unroll
        for (int j = 0; j < 4; ++j)
            dst[(lt + ty * 4 + i) * CHUNK + st + tx * 4 + j] = acc[i][j];
}

// =====================================================================
// y_intra
// =====================================================================
__global__ __launch_bounds__(256) void yintra_kernel()
{
    const int chunk = blockIdx.z, h = blockIdx.y, lt = blockIdx.x * 64;
    const int tid = threadIdx.x, tx = tid & 15, ty = tid >> 4;
    const int t0 = chunk * CHUNK;
    __shared__ float Ws[64][65];
    __shared__ float Xs[64][64];
    __shared__ float dal[64], das[64], dts[64];
    float acc[4][4] = {};
    if (tid < 64) dal[tid] = g_dacs[(t0 + lt + tid) * NH + h];
    const float* cbp = g_cb + chunk * CHUNK * CHUNK;

    for (int st = 0; st <= lt; st += 64) {
        __syncthreads();
        if (tid < 64) {
            das[tid] = g_dacs[(t0 + st + tid) * NH + h];
            dts[tid] = g_dt[(t0 + st + tid) * NH + h];
        }
        __syncthreads();
#pragma unroll
        for (int i = 0; i < 4; ++i) {
            int l = lt + ty * 4 + i;
#pragma unroll
            for (int j = 0; j < 4; ++j) {
                int s = st + tx * 4 + j;
                float w = 0.f;
                if (s <= l)
                    w = cbp[l * CHUNK + s] *
                        expf(dal[ty * 4 + i] - das[tx * 4 + j]) * dts[tx * 4 + j];
                Ws[ty * 4 + i][tx * 4 + j] = w;
            }
        }
#pragma unroll
        for (int rr = 0; rr < 4; ++rr) {
            int srow = rr * 16 + ty;
            *(float4*)&Xs[srow][tx * 4] =
                *(const float4*)&g_xbc[(size_t)(t0 + st + srow) * CONVD + h * HD + tx * 4];
        }
        __syncthreads();
#pragma unroll
        for (int kk = 0; kk < 64; ++kk) {
            float4 b = *(const float4*)&Xs[kk][tx * 4];
#pragma unroll
            for (int i = 0; i < 4; ++i) {
                float a = Ws[ty * 4 + i][kk];
                acc[i][0] = fmaf(a, b.x, acc[i][0]);
                acc[i][1] = fmaf(a, b.y, acc[i][1]);
                acc[i][2] = fmaf(a, b.z, acc[i][2]);
                acc[i][3] = fmaf(a, b.w, acc[i][3]);
            }
        }
    }
#pragma unroll
    for (int i = 0; i < 4; ++i) {
        int t = t0 + lt + ty * 4 + i;
        *(float4*)&g_y[(size_t)t * DI + h * HD + tx * 4] =
            make_float4(acc[i][0], acc[i][1], acc[i][2], acc[i][3]);
    }
}

// =====================================================================
// per-chunk states
// =====================================================================
__global__ __launch_bounds__(256) void states_kernel()
{
    const int h = blockIdx.x, chunk = blockIdx.y;
    const int tid = threadIdx.x, tx = tid & 15, ty = tid >> 4;
    const int t0 = chunk * CHUNK;
    __shared__ float Xt[32][64];
    __shared__ float Bt[32][128];
    __shared__ float coef[32];
    float acc[4][8] = {};
    const float dacs_last = g_dacs[(t0 + CHUNK - 1) * NH + h];

    for (int l0 = 0; l0 < CHUNK; l0 += 32) {
        __syncthreads();
        if (tid < 32) {
            int t = t0 + l0 + tid;
            coef[tid] = g_dt[t * NH + h] * expf(dacs_last - g_dacs[t * NH + h]);
        }
        {
            int r = tid >> 3, c = (tid & 7) * 8;
            *(float4*)&Xt[r][c] =
                *(const float4*)&g_xbc[(size_t)(t0 + l0 + r) * CONVD + h * HD + c];
            *(float4*)&Xt[r][c + 4] =
                *(const float4*)&g_xbc[(size_t)(t0 + l0 + r) * CONVD + h * HD + c + 4];
            int c2 = (tid & 7) * 16;
#pragma unroll
            for (int q = 0; q < 4; ++q)
                *(float4*)&Bt[r][c2 + q * 4] =
                    *(const float4*)&g_xbc[(size_t)(t0 + l0 + r) * CONVD + DI + c2 + q * 4];
        }
        __syncthreads();
#pragma unroll
        for (int kk = 0; kk < 32; ++kk) {
            float ck = coef[kk];
            float a[4];
#pragma unroll
            for (int i = 0; i < 4; ++i) a[i] = Xt[kk][ty * 4 + i] * ck;
            float4 b0 = *(const float4*)&Bt[kk][tx * 8];
            float4 b1 = *(const float4*)&Bt[kk][tx * 8 + 4];
            float b[8] = {b0.x, b0.y, b0.z, b0.w, b1.x, b1.y, b1.z, b1.w};
#pragma unroll
            for (int i = 0; i < 4; ++i)
#pragma unroll
                for (int j = 0; j < 8; ++j)
                    acc[i][j] = fmaf(a[i], b[j], acc[i][j]);
        }
    }
    float* dst = g_states + (size_t)(chunk * NH + h) * HD * DS;
#pragma unroll
    for (int i = 0; i < 4; ++i) {
        int p = ty * 4 + i;
#pragma unroll
        for (int j = 0; j < 8; j += 4)
            *(float4*)&dst[p * DS + tx * 8 + j] =
                make_float4(acc[i][j], acc[i][j + 1], acc[i][j + 2], acc[i][j + 3]);
    }
}

// =====================================================================
// cross-chunk scan
// =====================================================================
__global__ void scan_kernel()
{
    const int idx = blockIdx.x * blockDim.x + threadIdx.x;
    const int h = idx / (HD * DS);
    float S = 0.f;
#pragma unroll
    for (int c = 0; c < NC; ++c) {
        g_sprev[(size_t)c * (NH * HD * DS) + idx] = S;
        float cd = expf(g_dacs[(c * CHUNK + CHUNK - 1) * NH + h]);
        S = fmaf(cd, S, g_states[(size_t)c * (NH * HD * DS) + idx]);
    }
}

// =====================================================================
// y_inter + gate
// =====================================================================
__global__ __launch_bounds__(256) void yinter_kernel(const float* __restrict__ Dp)
{
    const int chunk = blockIdx.z, h = blockIdx.y, lt = blockIdx.x * 64;
    const int tid = threadIdx.x, tx = tid & 15, ty = tid >> 4;
    const int t0 = chunk * CHUNK;
    __shared__ float Cs[16][65];
    __shared__ float Ss[16][65];
    float acc[4][4] = {};
    const float* sp = g_sprev + (size_t)(chunk * NH + h) * HD * DS;
    const int lr = tid >> 2, nc = (tid & 3) * 4;

    for (int n0 = 0; n0 < DS; n0 += 16) {
        __syncthreads();
        {
            float4 cv = *(const float4*)&g_xbc[(size_t)(t0 + lt + lr) * CONVD + DI + DS + n0 + nc];
            Cs[nc + 0][lr] = cv.x; Cs[nc + 1][lr] = cv.y;
            Cs[nc + 2][lr] = cv.z; Cs[nc + 3][lr] = cv.w;
            float4 sv = *(const float4*)&sp[lr * DS + n0 + nc];
            Ss[nc + 0][lr] = sv.x; Ss[nc + 1][lr] = sv.y;
            Ss[nc + 2][lr] = sv.z; Ss[nc + 3][lr] = sv.w;
        }
        __syncthreads();
#pragma unroll
        for (int kk = 0; kk < 16; ++kk) {
            float a[4], b[4];
#pragma unroll
            for (int i = 0; i < 4; ++i) a[i] = Cs[kk][ty * 4 + i];
#pragma unroll
            for (int j = 0; j < 4; ++j) b[j] = Ss[kk][tx * 4 + j];
#pragma unroll
            for (int i = 0; i < 4; ++i)
#pragma unroll
                for (int j = 0; j < 4; ++j)
                    acc[i][j] = fmaf(a[i], b[j], acc[i][j]);
        }
    }

    const float Dh = Dp[h];
#pragma unroll
    for (int i = 0; i < 4; ++i) {
        int t = t0 + lt + ty * 4 + i;
        float esc = expf(g_dacs[t * NH + h]);
#pragma unroll
        for (int j = 0; j < 4; ++j) {
            int col = h * HD + tx * 4 + j;
            float x = g_xbc[(size_t)t * CONVD + col];
            float z = g_zxbcdt[(size_t)t * DPROJ + col];
            float yv = g_y[(size_t)t * DI + col] + acc[i][j] * esc + x * Dh;
            float gate = z / (1.f + expf(-z));
            g_y[(size_t)t * DI + col] = yv * gate;
        }
    }
}

// =====================================================================
// RMSNorm in place
// =====================================================================
__global__ void rmsnorm_kernel(const float* __restrict__ norm_w)
{
    const int t = blockIdx.x;
    float* row = g_y + (size_t)t * DI;
    float ss = 0.f;
    for (int c = threadIdx.x; c < DI; c += 256) {
        float v = row[c];
        ss = fmaf(v, v, ss);
    }
    __shared__ float red[256];
    red[threadIdx.x] = ss;
    __syncthreads();
    for (int o = 128; o > 0; o >>= 1) {
        if (threadIdx.x < o) red[threadIdx.x] += red[threadIdx.x + o];
        __syncthreads();
    }
    const float r = rsqrtf(red[0] / (float)DI + RMS_EPS);
    for (int c = threadIdx.x; c < DI; c += 256)
        row[c] = row[c] * r * norm_w[c];
}

// =====================================================================
// launch
// =====================================================================
extern "C" void kernel_launch(void* const* d_in, const int* in_sizes, int n_in,
                              void* d_out, int out_size)
{
    const float* hs   = (const float*)d_in[0];
    const float* win  = (const float*)d_in[1];
    const float* cw   = (const float*)d_in[2];
    const float* cbv  = (const float*)d_in[3];
    const float* Av   = (const float*)d_in[4];
    const float* Dp   = (const float*)d_in[5];
    const float* dtb  = (const float*)d_in[6];
    const float* nw   = (const float*)d_in[7];
    const float* wout = (const float*)d_in[8];
    float* out = (float*)d_out;

    gemm_in_kernel<<<dim3((DPROJ + 127) / 128, T_LEN / 128), 256>>>(hs, win);
    conv_silu_kernel<<<dim3(CONVD / 256, T_LEN), 256>>>(cw, cbv);
    dt_scan_kernel<<<NC * NH, CHUNK>>>(Av, dtb);
    cb_kernel<<<dim3(4, 4, NC), 256>>>();
    yintra_kernel<<<dim3(4, NH, NC), 256>>>();
    states_kernel<<<dim3(NH, NC), 256>>>();
    scan_kernel<<<(NH * HD * DS) / 256, 256>>>();
    yinter_kernel<<<dim3(4, NH, NC), 256>>>(Dp);
    rmsnorm_kernel<<<T_LEN, 256>>>(nw);
    gemm_out_kernel<<<dim3(DM / 128, T_LEN / 128), 256>>>(wout, out);
}

// round 11
// speedup vs baseline: 1.6919x; 1.5071x over previous
#include <cuda_runtime.h>
#include <mma.h>
#include <math.h>
#include <stdint.h>

using namespace nvcuda;

// ---------------- problem constants ----------------
#define T_LEN 4096
#define DM    2048
#define DI    4096
#define NH    64
#define HD    64
#define DS    128
#define CHUNK 256
#define NC    16
#define CONVD 4352
#define DPROJ 8512
#define ZLD   8576          // padded row stride for zxbcdt (67*128)
#define RMS_EPS 1e-5f

// ---------------- scratch ----------------
static __device__ float g_zxbcdt[(size_t)T_LEN * ZLD];
static __device__ float g_xbc[(size_t)T_LEN * CONVD];
static __device__ float g_dt[T_LEN * NH];
static __device__ float g_dacs[T_LEN * NH];
static __device__ float g_cb[NC * CHUNK * CHUNK];
static __device__ float g_states[NC * NH * HD * DS];
static __device__ float g_sprev[NC * NH * HD * DS];
static __device__ float g_y[(size_t)T_LEN * DI];

// =====================================================================
// integer-only fp32 -> bf16 hi/lo split (round-to-nearest-even)
// =====================================================================
__device__ __forceinline__ uint32_t bfsplit(float v, uint32_t& lo16) {
    uint32_t u = __float_as_uint(v);
    uint32_t hr = (u + 0x7FFFu + ((u >> 16) & 1u)) & 0xFFFF0000u;
    float r = v - __uint_as_float(hr);
    uint32_t ur = __float_as_uint(r);
    lo16 = (ur + 0x7FFFu + ((ur >> 16) & 1u)) >> 16;
    return hr >> 16;
}

__device__ __forceinline__ void cvt8(const float4& p, const float4& q,
                                     uint4& hi, uint4& lo) {
    uint32_t l0, l1, l2, l3, l4, l5, l6, l7;
    uint32_t h0 = bfsplit(p.x, l0), h1 = bfsplit(p.y, l1);
    uint32_t h2 = bfsplit(p.z, l2), h3 = bfsplit(p.w, l3);
    uint32_t h4 = bfsplit(q.x, l4), h5 = bfsplit(q.y, l5);
    uint32_t h6 = bfsplit(q.z, l6), h7 = bfsplit(q.w, l7);
    hi = make_uint4(h0 | (h1 << 16), h2 | (h3 << 16), h4 | (h5 << 16), h6 | (h7 << 16));
    lo = make_uint4(l0 | (l1 << 16), l2 | (l3 << 16), l4 | (l5 << 16), l6 | (l7 << 16));
}

// =====================================================================
// wmma split-bf16 GEMM: C[M,*] = A[M,K] @ B[Nrows,K]^T (fp32 in/out)
// acc = Ahi*Bhi + Ahi*Blo + Alo*Bhi  (3-term split, err ~2^-16)
// CTA 128x128, BK=16, 8 warps (warp tile 32x64), double-buffered smem.
// smem tiles [128][40] bf16: cols 0-15 = hi(k), 16-31 = lo(k), ld=40.
// Caller guarantees all output stores in-bounds (padded ldc or exact N).
// =====================================================================
#define SLD 40

__device__ __forceinline__ void gemm_wmma_body(
    const float* __restrict__ A, const float* __restrict__ B,
    float* __restrict__ C, int NrowsB, int K, int ldc)
{
    __shared__ __align__(16) __nv_bfloat16 sA[2][128 * SLD];
    __shared__ __align__(16) __nv_bfloat16 sB[2][128 * SLD];

    const int tid  = threadIdx.x;
    const int wid  = tid >> 5;
    const int wm   = wid & 3;            // 4 warp-rows of 32
    const int wn   = wid >> 2;           // 2 warp-cols of 64
    const int bm   = blockIdx.y * 128;
    const int bn   = blockIdx.x * 128;
    const int lr   = tid >> 1;           // 0..127 loader row
    const int lc   = (tid & 1) * 8;      // 0 or 8 loader k-offset
    const int NI   = K >> 4;

    const float* Ap = A + (size_t)(bm + lr) * K + lc;
    const float* Bp = B + (size_t)(bn + lr) * K + lc;
    const bool bvalid = (bn + lr) < NrowsB;

    wmma::fragment<wmma::accumulator, 16, 16, 16, float> fc[2][4];
#pragma unroll
    for (int mt = 0; mt < 2; ++mt)
#pragma unroll
        for (int nt = 0; nt < 4; ++nt) wmma::fill_fragment(fc[mt][nt], 0.f);

    float4 ra0, ra1, rb0, rb1;
    const float4 z4 = make_float4(0.f, 0.f, 0.f, 0.f);

#define PF(it) do {                                                    \
        const float* _a = Ap + ((it) << 4);                            \
        ra0 = *(const float4*)(_a);                                    \
        ra1 = *(const float4*)(_a + 4);                                \
        if (bvalid) {                                                  \
            const float* _b = Bp + ((it) << 4);                        \
            rb0 = *(const float4*)(_b);                                \
            rb1 = *(const float4*)(_b + 4);                            \
        } else { rb0 = z4; rb1 = z4; }                                 \
    } while (0)

#define ST(buf) do {                                                   \
        uint4 _hi, _lo;                                                \
        cvt8(ra0, ra1, _hi, _lo);                                      \
        *(uint4*)&sA[buf][lr * SLD + lc]      = _hi;                   \
        *(uint4*)&sA[buf][lr * SLD + 16 + lc] = _lo;                   \
        cvt8(rb0, rb1, _hi, _lo);                                      \
        *(uint4*)&sB[buf][lr * SLD + lc]      = _hi;                   \
        *(uint4*)&sB[buf][lr * SLD + 16 + lc] = _lo;                   \
    } while (0)

    PF(0);
    ST(0);
    __syncthreads();

    for (int it = 0; it < NI; ++it) {
        const int buf = it & 1;
        if (it + 1 < NI) PF(it + 1);

        const __nv_bfloat16* pA = sA[buf];
        const __nv_bfloat16* pB = sB[buf];

        wmma::fragment<wmma::matrix_a, 16, 16, 16, __nv_bfloat16, wmma::row_major> fah0, fah1, fal0, fal1;
        wmma::load_matrix_sync(fah0, pA + (wm * 32) * SLD, SLD);
        wmma::load_matrix_sync(fah1, pA + (wm * 32 + 16) * SLD, SLD);
        wmma::load_matrix_sync(fal0, pA + (wm * 32) * SLD + 16, SLD);
        wmma::load_matrix_sync(fal1, pA + (wm * 32 + 16) * SLD + 16, SLD);

#pragma unroll
        for (int nt = 0; nt < 4; ++nt) {
            wmma::fragment<wmma::matrix_b, 16, 16, 16, __nv_bfloat16, wmma::col_major> fb;
            // pass 1 + 3: b_hi with a_hi and a_lo
            wmma::load_matrix_sync(fb, pB + (wn * 64 + nt * 16) * SLD, SLD);
            wmma::mma_sync(fc[0][nt], fah0, fb, fc[0][nt]);
            wmma::mma_sync(fc[1][nt], fah1, fb, fc[1][nt]);
            wmma::mma_sync(fc[0][nt], fal0, fb, fc[0][nt]);
            wmma::mma_sync(fc[1][nt], fal1, fb, fc[1][nt]);
            // pass 2: b_lo with a_hi
            wmma::load_matrix_sync(fb, pB + (wn * 64 + nt * 16) * SLD + 16, SLD);
            wmma::mma_sync(fc[0][nt], fah0, fb, fc[0][nt]);
            wmma::mma_sync(fc[1][nt], fah1, fb, fc[1][nt]);
        }

        if (it + 1 < NI) {
            ST(buf ^ 1);
            __syncthreads();
        }
    }

#pragma unroll
    for (int mt = 0; mt < 2; ++mt)
#pragma unroll
        for (int nt = 0; nt < 4; ++nt) {
            float* cp = C + (size_t)(bm + wm * 32 + mt * 16) * ldc
                          + (bn + wn * 64 + nt * 16);
            wmma::store_matrix_sync(cp, fc[mt][nt], ldc, wmma::mem_row_major);
        }
#undef PF
#undef ST
}

__global__ __launch_bounds__(256) void gemm_in_kernel(
    const float* __restrict__ hs, const float* __restrict__ w)
{
    gemm_wmma_body(hs, w, g_zxbcdt, DPROJ, DM, ZLD);
}

__global__ __launch_bounds__(256) void gemm_out_kernel(
    const float* __restrict__ w, float* __restrict__ out)
{
    gemm_wmma_body(g_y, w, out, DM, DI, DM);
}

// =====================================================================
// Causal depthwise conv (width 4) + SiLU
// =====================================================================
__global__ void conv_silu_kernel(const float* __restrict__ conv_w,
                                 const float* __restrict__ conv_b)
{
    const int c = blockIdx.x * 256 + threadIdx.x;
    const int t = blockIdx.y;
    float acc = conv_b[c];
#pragma unroll
    for (int k = 0; k < 4; ++k) {
        int tt = t - 3 + k;
        if (tt >= 0)
            acc = fmaf(conv_w[c * 4 + k],
                       g_zxbcdt[(size_t)tt * ZLD + DI + c], acc);
    }
    g_xbc[(size_t)t * CONVD + c] = acc / (1.f + expf(-acc));
}

// =====================================================================
// softplus + per-chunk cumsum of dt*A
// =====================================================================
__global__ void dt_scan_kernel(const float* __restrict__ Av,
                               const float* __restrict__ dtb)
{
    const int c = blockIdx.x / NH, h = blockIdx.x % NH;
    const int l = threadIdx.x;
    const int t = c * CHUNK + l;
    float xv = g_zxbcdt[(size_t)t * ZLD + DI + CONVD + h] + dtb[h];
    float dtv = (xv > 15.f) ? xv : log1pf(expf(xv));
    g_dt[t * NH + h] = dtv;

    __shared__ float sb[CHUNK];
    sb[l] = dtv * Av[h];
    __syncthreads();
    for (int off = 1; off < CHUNK; off <<= 1) {
        float v = (l >= off) ? sb[l - off] : 0.f;
        __syncthreads();
        sb[l] += v;
        __syncthreads();
    }
    g_dacs[t * NH + h] = sb[l];
}

// =====================================================================
// CB = C @ B^T per chunk (lower-triangular tiles only)
// =====================================================================
__global__ __launch_bounds__(256) void cb_kernel()
{
    if (blockIdx.x > blockIdx.y) return;
    const int chunk = blockIdx.z;
    const int lt = blockIdx.y * 64, st = blockIdx.x * 64;
    const int tid = threadIdx.x, tx = tid & 15, ty = tid >> 4;
    const int t0 = chunk * CHUNK;
    __shared__ float Cs[16][65];
    __shared__ float Bs[16][65];
    float acc[4][4] = {};
    const int lr = tid >> 2, kc = (tid & 3) * 4;

    for (int k0 = 0; k0 < DS; k0 += 16) {
        __syncthreads();
        float4 cv = *(const float4*)&g_xbc[(size_t)(t0 + lt + lr) * CONVD + DI + DS + k0 + kc];
        Cs[kc + 0][lr] = cv.x; Cs[kc + 1][lr] = cv.y;
        Cs[kc + 2][lr] = cv.z; Cs[kc + 3][lr] = cv.w;
        float4 bv = *(const float4*)&g_xbc[(size_t)(t0 + st + lr) * CONVD + DI + k0 + kc];
        Bs[kc + 0][lr] = bv.x; Bs[kc + 1][lr] = bv.y;
        Bs[kc + 2][lr] = bv.z; Bs[kc + 3][lr] = bv.w;
        __syncthreads();
#pragma unroll
        for (int kk = 0; kk < 16; ++kk) {
            float a[4], b[4];
#pragma unroll
            for (int i = 0; i < 4; ++i) a[i] = Cs[kk][ty * 4 + i];
#pragma unroll
            for (int j = 0; j < 4; ++j) b[j] = Bs[kk][tx * 4 + j];
#pragma unroll
            for (int i = 0; i < 4; ++i)
#pragma unroll
                for (int j = 0; j < 4; ++j)
                    acc[i][j] = fmaf(a[i], b[j], acc[i][j]);
        }
    }
    float* dst = g_cb + chunk * CHUNK * CHUNK;
#pragma unroll
    for (int i = 0; i < 4; ++i)
#pragma unroll
        for (int j = 0; j < 4; ++j)
            dst[(lt + ty * 4 + i) * CHUNK + st + tx * 4 + j] = acc[i][j];
}

// =====================================================================
// y_intra
// =====================================================================
__global__ __launch_bounds__(256) void yintra_kernel()
{
    const int chunk = blockIdx.z, h = blockIdx.y, lt = blockIdx.x * 64;
    const int tid = threadIdx.x, tx = tid & 15, ty = tid >> 4;
    const int t0 = chunk * CHUNK;
    __shared__ float Ws[64][65];
    __shared__ float Xs[64][64];
    __shared__ float dal[64], das[64], dts[64];
    float acc[4][4] = {};
    if (tid < 64) dal[tid] = g_dacs[(t0 + lt + tid) * NH + h];
    const float* cbp = g_cb + chunk * CHUNK * CHUNK;

    for (int st = 0; st <= lt; st += 64) {
        __syncthreads();
        if (tid < 64) {
            das[tid] = g_dacs[(t0 + st + tid) * NH + h];
            dts[tid] = g_dt[(t0 + st + tid) * NH + h];
        }
        __syncthreads();
#pragma unroll
        for (int i = 0; i < 4; ++i) {
            int l = lt + ty * 4 + i;
#pragma unroll
            for (int j = 0; j < 4; ++j) {
                int s = st + tx * 4 + j;
                float w = 0.f;
                if (s <= l)
                    w = cbp[l * CHUNK + s] *
                        expf(dal[ty * 4 + i] - das[tx * 4 + j]) * dts[tx * 4 + j];
                Ws[ty * 4 + i][tx * 4 + j] = w;
            }
        }
#pragma unroll
        for (int rr = 0; rr < 4; ++rr) {
            int srow = rr * 16 + ty;
            *(float4*)&Xs[srow][tx * 4] =
                *(const float4*)&g_xbc[(size_t)(t0 + st + srow) * CONVD + h * HD + tx * 4];
        }
        __syncthreads();
#pragma unroll
        for (int kk = 0; kk < 64; ++kk) {
            float4 b = *(const float4*)&Xs[kk][tx * 4];
#pragma unroll
            for (int i = 0; i < 4; ++i) {
                float a = Ws[ty * 4 + i][kk];
                acc[i][0] = fmaf(a, b.x, acc[i][0]);
                acc[i][1] = fmaf(a, b.y, acc[i][1]);
                acc[i][2] = fmaf(a, b.z, acc[i][2]);
                acc[i][3] = fmaf(a, b.w, acc[i][3]);
            }
        }
    }
#pragma unroll
    for (int i = 0; i < 4; ++i) {
        int t = t0 + lt + ty * 4 + i;
        *(float4*)&g_y[(size_t)t * DI + h * HD + tx * 4] =
            make_float4(acc[i][0], acc[i][1], acc[i][2], acc[i][3]);
    }
}

// =====================================================================
// per-chunk states
// =====================================================================
__global__ __launch_bounds__(256) void states_kernel()
{
    const int h = blockIdx.x, chunk = blockIdx.y;
    const int tid = threadIdx.x, tx = tid & 15, ty = tid >> 4;
    const int t0 = chunk * CHUNK;
    __shared__ float Xt[32][64];
    __shared__ float Bt[32][128];
    __shared__ float coef[32];
    float acc[4][8] = {};
    const float dacs_last = g_dacs[(t0 + CHUNK - 1) * NH + h];

    for (int l0 = 0; l0 < CHUNK; l0 += 32) {
        __syncthreads();
        if (tid < 32) {
            int t = t0 + l0 + tid;
            coef[tid] = g_dt[t * NH + h] * expf(dacs_last - g_dacs[t * NH + h]);
        }
        {
            int r = tid >> 3, c = (tid & 7) * 8;
            *(float4*)&Xt[r][c] =
                *(const float4*)&g_xbc[(size_t)(t0 + l0 + r) * CONVD + h * HD + c];
            *(float4*)&Xt[r][c + 4] =
                *(const float4*)&g_xbc[(size_t)(t0 + l0 + r) * CONVD + h * HD + c + 4];
            int c2 = (tid & 7) * 16;
#pragma unroll
            for (int q = 0; q < 4; ++q)
                *(float4*)&Bt[r][c2 + q * 4] =
                    *(const float4*)&g_xbc[(size_t)(t0 + l0 + r) * CONVD + DI + c2 + q * 4];
        }
        __syncthreads();
#pragma unroll
        for (int kk = 0; kk < 32; ++kk) {
            float ck = coef[kk];
            float a[4];
#pragma unroll
            for (int i = 0; i < 4; ++i) a[i] = Xt[kk][ty * 4 + i] * ck;
            float4 b0 = *(const float4*)&Bt[kk][tx * 8];
            float4 b1 = *(const float4*)&Bt[kk][tx * 8 + 4];
            float b[8] = {b0.x, b0.y, b0.z, b0.w, b1.x, b1.y, b1.z, b1.w};
#pragma unroll
            for (int i = 0; i < 4; ++i)
#pragma unroll
                for (int j = 0; j < 8; ++j)
                    acc[i][j] = fmaf(a[i], b[j], acc[i][j]);
        }
    }
    float* dst = g_states + (size_t)(chunk * NH + h) * HD * DS;
#pragma unroll
    for (int i = 0; i < 4; ++i) {
        int p = ty * 4 + i;
#pragma unroll
        for (int j = 0; j < 8; j += 4)
            *(float4*)&dst[p * DS + tx * 8 + j] =
                make_float4(acc[i][j], acc[i][j + 1], acc[i][j + 2], acc[i][j + 3]);
    }
}

// =====================================================================
// cross-chunk scan
// =====================================================================
__global__ void scan_kernel()
{
    const int idx = blockIdx.x * blockDim.x + threadIdx.x;
    const int h = idx / (HD * DS);
    float S = 0.f;
#pragma unroll
    for (int c = 0; c < NC; ++c) {
        g_sprev[(size_t)c * (NH * HD * DS) + idx] = S;
        float cd = expf(g_dacs[(c * CHUNK + CHUNK - 1) * NH + h]);
        S = fmaf(cd, S, g_states[(size_t)c * (NH * HD * DS) + idx]);
    }
}

// =====================================================================
// y_inter + gate
// =====================================================================
__global__ __launch_bounds__(256) void yinter_kernel(const float* __restrict__ Dp)
{
    const int chunk = blockIdx.z, h = blockIdx.y, lt = blockIdx.x * 64;
    const int tid = threadIdx.x, tx = tid & 15, ty = tid >> 4;
    const int t0 = chunk * CHUNK;
    __shared__ float Cs[16][65];
    __shared__ float Ss[16][65];
    float acc[4][4] = {};
    const float* sp = g_sprev + (size_t)(chunk * NH + h) * HD * DS;
    const int lr = tid >> 2, nc = (tid & 3) * 4;

    for (int n0 = 0; n0 < DS; n0 += 16) {
        __syncthreads();
        {
            float4 cv = *(const float4*)&g_xbc[(size_t)(t0 + lt + lr) * CONVD + DI + DS + n0 + nc];
            Cs[nc + 0][lr] = cv.x; Cs[nc + 1][lr] = cv.y;
            Cs[nc + 2][lr] = cv.z; Cs[nc + 3][lr] = cv.w;
            float4 sv = *(const float4*)&sp[lr * DS + n0 + nc];
            Ss[nc + 0][lr] = sv.x; Ss[nc + 1][lr] = sv.y;
            Ss[nc + 2][lr] = sv.z; Ss[nc + 3][lr] = sv.w;
        }
        __syncthreads();
#pragma unroll
        for (int kk = 0; kk < 16; ++kk) {
            float a[4], b[4];
#pragma unroll
            for (int i = 0; i < 4; ++i) a[i] = Cs[kk][ty * 4 + i];
#pragma unroll
            for (int j = 0; j < 4; ++j) b[j] = Ss[kk][tx * 4 + j];
#pragma unroll
            for (int i = 0; i < 4; ++i)
#pragma unroll
                for (int j = 0; j < 4; ++j)
                    acc[i][j] = fmaf(a[i], b[j], acc[i][j]);
        }
    }

    const float Dh = Dp[h];
#pragma unroll
    for (int i = 0; i < 4; ++i) {
        int t = t0 + lt + ty * 4 + i;
        float esc = expf(g_dacs[t * NH + h]);
#pragma unroll
        for (int j = 0; j < 4; ++j) {
            int col = h * HD + tx * 4 + j;
            float x = g_xbc[(size_t)t * CONVD + col];
            float z = g_zxbcdt[(size_t)t * ZLD + col];
            float yv = g_y[(size_t)t * DI + col] + acc[i][j] * esc + x * Dh;
            float gate = z / (1.f + expf(-z));
            g_y[(size_t)t * DI + col] = yv * gate;
        }
    }
}

// =====================================================================
// RMSNorm in place
// =====================================================================
__global__ void rmsnorm_kernel(const float* __restrict__ norm_w)
{
    const int t = blockIdx.x;
    float* row = g_y + (size_t)t * DI;
    float ss = 0.f;
    for (int c = threadIdx.x; c < DI; c += 256) {
        float v = row[c];
        ss = fmaf(v, v, ss);
    }
    __shared__ float red[256];
    red[threadIdx.x] = ss;
    __syncthreads();
    for (int o = 128; o > 0; o >>= 1) {
        if (threadIdx.x < o) red[threadIdx.x] += red[threadIdx.x + o];
        __syncthreads();
    }
    const float r = rsqrtf(red[0] / (float)DI + RMS_EPS);
    for (int c = threadIdx.x; c < DI; c += 256)
        row[c] = row[c] * r * norm_w[c];
}

// =====================================================================
// launch
// =====================================================================
extern "C" void kernel_launch(void* const* d_in, const int* in_sizes, int n_in,
                              void* d_out, int out_size)
{
    const float* hs   = (const float*)d_in[0];
    const float* win  = (const float*)d_in[1];
    const float* cw   = (const float*)d_in[2];
    const float* cbv  = (const float*)d_in[3];
    const float* Av   = (const float*)d_in[4];
    const float* Dp   = (const float*)d_in[5];
    const float* dtb  = (const float*)d_in[6];
    const float* nw   = (const float*)d_in[7];
    const float* wout = (const float*)d_in[8];
    float* out = (float*)d_out;

    gemm_in_kernel<<<dim3(ZLD / 128, T_LEN / 128), 256>>>(hs, win);
    conv_silu_kernel<<<dim3(CONVD / 256, T_LEN), 256>>>(cw, cbv);
    dt_scan_kernel<<<NC * NH, CHUNK>>>(Av, dtb);
    cb_kernel<<<dim3(4, 4, NC), 256>>>();
    yintra_kernel<<<dim3(4, NH, NC), 256>>>();
    states_kernel<<<dim3(NH, NC), 256>>>();
    scan_kernel<<<(NH * HD * DS) / 256, 256>>>();
    yinter_kernel<<<dim3(4, NH, NC), 256>>>(Dp);
    rmsnorm_kernel<<<T_LEN, 256>>>(nw);
    gemm_out_kernel<<<dim3(DM / 128, T_LEN / 128), 256>>>(wout, out);
}